// round 4
// baseline (speedup 1.0000x reference)
#include <cuda_runtime.h>
#include <cuda_bf16.h>
#include <cstdint>

// ============================================================================
// QuantizedPatternMatcher — bit-sliced popcount matcher, 2-kernel fused form.
//   q(v) = #edges v exceeds (3-bit code); matches[m,p] = #d q_x==q_pat
// Per u32 word (32 dims): eq = LOP3-chain(a0^b0, a1^b1, a2^b2) -> popc -> add.
// Argmax fused: key = (cnt<<10)|(1023-p); atomicMax per m; last CTA converts.
// R3: occupancy push (launch_bounds(256,4), split-B halves to cut live regs),
//     paired popc accumulation (IADD3) across unroll-2 w iterations.
// ============================================================================

static constexpr int M_TOTAL = 8192;
static constexpr int P_TOTAL = 1024;
static constexpr int D_DIM   = 512;
static constexpr int NW      = 16;              // u32 words per plane per row
static constexpr int TR      = 64;              // tile rows (both M and P)
static constexpr int MT      = M_TOTAL / TR;    // 128
static constexpr int PT      = P_TOTAL / TR;    // 16
static constexpr int TILE_U32 = NW * 3 * TR;    // 3072 u32 = 12 KB per tile
static constexpr int NCTAS   = MT * PT;         // 2048

__device__ __align__(16) uint32_t g_Acode[MT * TILE_U32];   // 1.5 MB
__device__ __align__(16) uint32_t g_Bcode[PT * TILE_U32];   // 192 KB
__device__ uint32_t g_key[M_TOTAL];
__device__ unsigned int g_ctr;

// NOR-of-xors via guaranteed 3-LOP3 chain.
__device__ __forceinline__ uint32_t eq3(uint32_t a0, uint32_t b0,
                                        uint32_t a1, uint32_t b1,
                                        uint32_t a2, uint32_t b2) {
    uint32_t x, y, z;
    asm("lop3.b32 %0, %1, %2, %3, 0x3C;" : "=r"(x) : "r"(a0), "r"(b0), "r"(0u)); // a^b
    asm("lop3.b32 %0, %1, %2, %3, 0xBE;" : "=r"(y) : "r"(a1), "r"(b1), "r"(x));  // (a^b)|c
    asm("lop3.b32 %0, %1, %2, %3, 0x41;" : "=r"(z) : "r"(a2), "r"(b2), "r"(y));  // ~((a^b)|c)
    return z;
}

// ------------------------------------------------------------- encoding ----
// One warp per (row, word). Ballots build 3 bitplanes. Tile layout
// [tile][w][plane][row_local(64)] -> match kernel copies are pure uint4 streams.
// Block 0 additionally zeroes g_key / g_ctr for this replay.
__global__ void __launch_bounds__(256) encode_kernel(
    const float* __restrict__ x, const float* __restrict__ pat,
    const float* __restrict__ edges) {
    if (blockIdx.x == 0) {
        for (int i = threadIdx.x; i < M_TOTAL; i += 256) g_key[i] = 0u;
        if (threadIdx.x == 0) g_ctr = 0u;
    }
    int gw   = blockIdx.x * 8 + (threadIdx.x >> 5);
    int lane = threadIdx.x & 31;

    const float* src;
    uint32_t* dst;
    int row, w;
    if (gw < M_TOTAL * NW) {
        src = x;   dst = g_Acode; row = gw >> 4; w = gw & 15;
    } else {
        gw -= M_TOTAL * NW;
        src = pat; dst = g_Bcode; row = gw >> 4; w = gw & 15;
    }

    float e0 = __ldg(edges + 0), e1 = __ldg(edges + 1), e2 = __ldg(edges + 2),
          e3 = __ldg(edges + 3), e4 = __ldg(edges + 4), e5 = __ldg(edges + 5),
          e6 = __ldg(edges + 6);
    float v = __ldg(src + (size_t)row * D_DIM + w * 32 + lane);
    int q = (v > e0) + (v > e1) + (v > e2) + (v > e3) + (v > e4) + (v > e5) + (v > e6);

    unsigned b0 = __ballot_sync(0xffffffffu, q & 1);
    unsigned b1 = __ballot_sync(0xffffffffu, q & 2);
    unsigned b2 = __ballot_sync(0xffffffffu, q & 4);
    if (lane == 0) {
        int rt = row >> 6, rl = row & 63;
        uint32_t* base = dst + (size_t)rt * TILE_U32 + (w * 3) * TR + rl;
        base[0]      = b0;
        base[TR]     = b1;
        base[2 * TR] = b2;
    }
}

// --------------------------------------------------------------- matcher ----
// CTA = 64M x 64P tile, 256 threads (tx 0..15 = p-group, ty 0..15 = m-group),
// each thread 4M x 4P. B fragment loaded in two uint2 halves to keep live
// registers ~55 so 4 CTAs/SM fit. w-loop processed in pairs so the two popc
// results per accumulator fuse into one IADD3.
__global__ void __launch_bounds__(256, 4) match_kernel(float* __restrict__ out) {
    __shared__ uint32_t sA[TILE_U32];
    __shared__ uint32_t sB[TILE_U32];
    __shared__ bool s_last;

    const int tid = threadIdx.x;
    const int pt = blockIdx.x, mt = blockIdx.y;

    const uint4* gA = reinterpret_cast<const uint4*>(g_Acode + (size_t)mt * TILE_U32);
    const uint4* gB = reinterpret_cast<const uint4*>(g_Bcode + (size_t)pt * TILE_U32);
    uint4* s4A = reinterpret_cast<uint4*>(sA);
    uint4* s4B = reinterpret_cast<uint4*>(sB);
#pragma unroll
    for (int i = 0; i < TILE_U32 / 4; i += 256) {
        s4A[i + tid] = gA[i + tid];
        s4B[i + tid] = gB[i + tid];
    }
    __syncthreads();

    const int tx = tid & 15;
    const int ty = tid >> 4;

    uint32_t acc[4][4];
#pragma unroll
    for (int mi = 0; mi < 4; mi++)
#pragma unroll
        for (int pi = 0; pi < 4; pi++) acc[mi][pi] = 0;

#pragma unroll 1
    for (int w = 0; w < NW; w += 2) {
        // A fragments for both w and w+1 (broadcast loads within warp).
        uint32_t a[2][3][4];
#pragma unroll
        for (int u = 0; u < 2; u++)
#pragma unroll
            for (int pl = 0; pl < 3; pl++) {
                uint4 av = *reinterpret_cast<const uint4*>(
                    &sA[((w + u) * 3 + pl) * TR + ty * 4]);
                a[u][pl][0] = av.x; a[u][pl][1] = av.y;
                a[u][pl][2] = av.z; a[u][pl][3] = av.w;
            }
        // B in two halves of 2 p-cols to bound live registers.
#pragma unroll
        for (int h = 0; h < 2; h++) {
            uint32_t b[2][3][2];
#pragma unroll
            for (int u = 0; u < 2; u++)
#pragma unroll
                for (int pl = 0; pl < 3; pl++) {
                    uint2 bv = *reinterpret_cast<const uint2*>(
                        &sB[((w + u) * 3 + pl) * TR + tx * 4 + h * 2]);
                    b[u][pl][0] = bv.x; b[u][pl][1] = bv.y;
                }
#pragma unroll
            for (int mi = 0; mi < 4; mi++)
#pragma unroll
                for (int pi = 0; pi < 2; pi++) {
                    uint32_t e0 = eq3(a[0][0][mi], b[0][0][pi],
                                      a[0][1][mi], b[0][1][pi],
                                      a[0][2][mi], b[0][2][pi]);
                    uint32_t e1 = eq3(a[1][0][mi], b[1][0][pi],
                                      a[1][1][mi], b[1][1][pi],
                                      a[1][2][mi], b[1][2][pi]);
                    // two popcs fuse with acc into IADD3
                    acc[mi][h * 2 + pi] += (uint32_t)__popc(e0) + (uint32_t)__popc(e1);
                }
        }
    }

    // key = (cnt<<10)|(1023-p): max == first-max (lowest index wins ties).
#pragma unroll
    for (int mi = 0; mi < 4; mi++) {
        uint32_t key = 0;
#pragma unroll
        for (int pi = 0; pi < 4; pi++) {
            int p = pt * TR + tx * 4 + (pi & 1) + (pi >> 1) * 2;  // == tx*4+pi order-free max
            uint32_t k = (acc[mi][pi] << 10) | (uint32_t)(1023 - p);
            key = key > k ? key : k;
        }
#pragma unroll
        for (int off = 8; off >= 1; off >>= 1) {   // reduce over the 16 tx lanes
            uint32_t o = __shfl_xor_sync(0xffffffffu, key, off);
            key = key > o ? key : o;
        }
        if (tx == 0) {
            int m = mt * TR + ty * 4 + mi;
            atomicMax(&g_key[m], key);
        }
    }

    // Last CTA converts keys -> (best_patterns, match_scores).
    __threadfence();
    if (tid == 0)
        s_last = (atomicAdd(&g_ctr, 1u) == (unsigned)(NCTAS - 1));
    __syncthreads();
    if (s_last) {
        __threadfence();   // acquire all g_key updates
        for (int m = tid; m < M_TOTAL; m += 256) {
            uint32_t best = g_key[m];
            out[m]           = (float)(1023u - (best & 1023u));
            out[M_TOTAL + m] = (float)(best >> 10) * (1.0f / 512.0f);
        }
    }
}

// ---------------------------------------------------------------- launch ----
extern "C" void kernel_launch(void* const* d_in, const int* in_sizes, int n_in,
                              void* d_out, int out_size) {
    const float* x     = (const float*)d_in[0];
    const float* pat   = (const float*)d_in[1];
    const float* edges = (const float*)d_in[2];

    // (8192 + 1024) rows * 16 words = 147456 warps -> 18432 blocks of 8 warps
    encode_kernel<<<(M_TOTAL + P_TOTAL) * NW / 8, 256>>>(x, pat, edges);
    match_kernel<<<dim3(PT, MT), 256>>>((float*)d_out);
}

// round 5
// speedup vs baseline: 1.0098x; 1.0098x over previous
#include <cuda_runtime.h>
#include <cuda_bf16.h>
#include <cstdint>

// ============================================================================
// QuantizedPatternMatcher — bit-sliced popcount matcher.
//   q(v) = #edges v exceeds (3-bit code); matches[m,p] = #d q_x==q_pat
// Per u32 word (32 dims): eq = LOP3-chain(a0^b0, a1^b1, a2^b2) -> popc -> add.
// Argmax fused: key = (cnt<<10)|(1023-p); atomicMax per m; last CTA converts.
// R4: 8Mx8P per thread (CTA tile 128x128) -> LDS:alu ratio 2:3 -> 1:3.
// ============================================================================

static constexpr int M_TOTAL = 8192;
static constexpr int P_TOTAL = 1024;
static constexpr int D_DIM   = 512;
static constexpr int NW      = 16;              // u32 words per plane per row
static constexpr int TR      = 128;             // tile rows (both M and P)
static constexpr int MT      = M_TOTAL / TR;    // 64
static constexpr int PT      = P_TOTAL / TR;    // 8
static constexpr int TILE_U32 = NW * 3 * TR;    // 6144 u32 = 24 KB per tile
static constexpr int NCTAS   = MT * PT;         // 512
static constexpr int SMEM_BYTES = 2 * TILE_U32 * 4;  // 48 KB

__device__ __align__(16) uint32_t g_Acode[MT * TILE_U32];   // 1.5 MB
__device__ __align__(16) uint32_t g_Bcode[PT * TILE_U32];   // 192 KB
__device__ uint32_t g_key[M_TOTAL];
__device__ unsigned int g_ctr;

// NOR-of-xors via guaranteed 3-LOP3 chain.
__device__ __forceinline__ uint32_t eq3(uint32_t a0, uint32_t b0,
                                        uint32_t a1, uint32_t b1,
                                        uint32_t a2, uint32_t b2) {
    uint32_t x, y, z;
    asm("lop3.b32 %0, %1, %2, %3, 0x3C;" : "=r"(x) : "r"(a0), "r"(b0), "r"(0u)); // a^b
    asm("lop3.b32 %0, %1, %2, %3, 0xBE;" : "=r"(y) : "r"(a1), "r"(b1), "r"(x));  // (a^b)|c
    asm("lop3.b32 %0, %1, %2, %3, 0x41;" : "=r"(z) : "r"(a2), "r"(b2), "r"(y));  // ~((a^b)|c)
    return z;
}

// ------------------------------------------------------------- encoding ----
// One warp per (row, word). Ballots build 3 bitplanes. Tile layout
// [tile][w][plane][row_local(128)] -> match kernel copies are uint4 streams.
// Block 0 additionally zeroes g_key / g_ctr for this replay.
__global__ void __launch_bounds__(256) encode_kernel(
    const float* __restrict__ x, const float* __restrict__ pat,
    const float* __restrict__ edges) {
    if (blockIdx.x == 0) {
        for (int i = threadIdx.x; i < M_TOTAL; i += 256) g_key[i] = 0u;
        if (threadIdx.x == 0) g_ctr = 0u;
    }
    int gw   = blockIdx.x * 8 + (threadIdx.x >> 5);
    int lane = threadIdx.x & 31;

    const float* src;
    uint32_t* dst;
    int row, w;
    if (gw < M_TOTAL * NW) {
        src = x;   dst = g_Acode; row = gw >> 4; w = gw & 15;
    } else {
        gw -= M_TOTAL * NW;
        src = pat; dst = g_Bcode; row = gw >> 4; w = gw & 15;
    }

    float e0 = __ldg(edges + 0), e1 = __ldg(edges + 1), e2 = __ldg(edges + 2),
          e3 = __ldg(edges + 3), e4 = __ldg(edges + 4), e5 = __ldg(edges + 5),
          e6 = __ldg(edges + 6);
    float v = __ldg(src + (size_t)row * D_DIM + w * 32 + lane);
    int q = (v > e0) + (v > e1) + (v > e2) + (v > e3) + (v > e4) + (v > e5) + (v > e6);

    unsigned b0 = __ballot_sync(0xffffffffu, q & 1);
    unsigned b1 = __ballot_sync(0xffffffffu, q & 2);
    unsigned b2 = __ballot_sync(0xffffffffu, q & 4);
    if (lane == 0) {
        int rt = row >> 7, rl = row & 127;
        uint32_t* base = dst + (size_t)rt * TILE_U32 + (w * 3) * TR + rl;
        base[0]      = b0;
        base[TR]     = b1;
        base[2 * TR] = b2;
    }
}

// --------------------------------------------------------------- matcher ----
// CTA = 128M x 128P tile, 256 threads (tx 0..15 p-group, ty 0..15 m-group),
// each thread 8M x 8P. B fragment in two 4-col halves keeps live regs ~110.
// Fused argmax -> atomicMax(g_key[m]); last CTA emits final output.
__global__ void __launch_bounds__(256, 2) match_kernel(float* __restrict__ out) {
    extern __shared__ __align__(16) uint32_t smem[];
    uint32_t* sA = smem;               // TILE_U32
    uint32_t* sB = smem + TILE_U32;    // TILE_U32
    __shared__ bool s_last;

    const int tid = threadIdx.x;
    const int pt = blockIdx.x, mt = blockIdx.y;

    const uint4* gA = reinterpret_cast<const uint4*>(g_Acode + (size_t)mt * TILE_U32);
    const uint4* gB = reinterpret_cast<const uint4*>(g_Bcode + (size_t)pt * TILE_U32);
    uint4* s4A = reinterpret_cast<uint4*>(sA);
    uint4* s4B = reinterpret_cast<uint4*>(sB);
#pragma unroll
    for (int i = 0; i < TILE_U32 / 4; i += 256) {
        s4A[i + tid] = gA[i + tid];
        s4B[i + tid] = gB[i + tid];
    }
    __syncthreads();

    const int tx = tid & 15;
    const int ty = tid >> 4;

    uint32_t acc[8][8];
#pragma unroll
    for (int mi = 0; mi < 8; mi++)
#pragma unroll
        for (int pi = 0; pi < 8; pi++) acc[mi][pi] = 0;

#pragma unroll 1
    for (int w = 0; w < NW; w++) {
        uint32_t a[3][8];
#pragma unroll
        for (int pl = 0; pl < 3; pl++) {
            const int rowbase = (w * 3 + pl) * TR + ty * 8;
            uint4 a0 = *reinterpret_cast<const uint4*>(&sA[rowbase]);
            uint4 a1 = *reinterpret_cast<const uint4*>(&sA[rowbase + 4]);
            a[pl][0] = a0.x; a[pl][1] = a0.y; a[pl][2] = a0.z; a[pl][3] = a0.w;
            a[pl][4] = a1.x; a[pl][5] = a1.y; a[pl][6] = a1.z; a[pl][7] = a1.w;
        }
#pragma unroll
        for (int h = 0; h < 2; h++) {
            uint32_t b[3][4];
#pragma unroll
            for (int pl = 0; pl < 3; pl++) {
                uint4 bv = *reinterpret_cast<const uint4*>(
                    &sB[(w * 3 + pl) * TR + tx * 8 + h * 4]);
                b[pl][0] = bv.x; b[pl][1] = bv.y; b[pl][2] = bv.z; b[pl][3] = bv.w;
            }
#pragma unroll
            for (int mi = 0; mi < 8; mi++)
#pragma unroll
                for (int pi = 0; pi < 4; pi++)
                    acc[mi][h * 4 + pi] += (uint32_t)__popc(
                        eq3(a[0][mi], b[0][pi], a[1][mi], b[1][pi],
                            a[2][mi], b[2][pi]));
        }
    }

    // key = (cnt<<10)|(1023-p): max == first-max (lowest index wins ties).
#pragma unroll
    for (int mi = 0; mi < 8; mi++) {
        uint32_t key = 0;
#pragma unroll
        for (int pi = 0; pi < 8; pi++) {
            int p = pt * TR + tx * 8 + pi;
            uint32_t k = (acc[mi][pi] << 10) | (uint32_t)(1023 - p);
            key = key > k ? key : k;
        }
#pragma unroll
        for (int off = 8; off >= 1; off >>= 1) {   // reduce over the 16 tx lanes
            uint32_t o = __shfl_xor_sync(0xffffffffu, key, off);
            key = key > o ? key : o;
        }
        if (tx == 0) {
            int m = mt * TR + ty * 8 + mi;
            atomicMax(&g_key[m], key);
        }
    }

    // Last CTA converts keys -> (best_patterns, match_scores).
    __threadfence();
    if (tid == 0)
        s_last = (atomicAdd(&g_ctr, 1u) == (unsigned)(NCTAS - 1));
    __syncthreads();
    if (s_last) {
        __threadfence();   // acquire all g_key updates
        for (int m = tid; m < M_TOTAL; m += 256) {
            uint32_t best = g_key[m];
            out[m]           = (float)(1023u - (best & 1023u));
            out[M_TOTAL + m] = (float)(best >> 10) * (1.0f / 512.0f);
        }
    }
}

// ---------------------------------------------------------------- launch ----
extern "C" void kernel_launch(void* const* d_in, const int* in_sizes, int n_in,
                              void* d_out, int out_size) {
    const float* x     = (const float*)d_in[0];
    const float* pat   = (const float*)d_in[1];
    const float* edges = (const float*)d_in[2];

    cudaFuncSetAttribute(match_kernel,
                         cudaFuncAttributeMaxDynamicSharedMemorySize, SMEM_BYTES);

    // (8192 + 1024) rows * 16 words = 147456 warps -> 18432 blocks of 8 warps
    encode_kernel<<<(M_TOTAL + P_TOTAL) * NW / 8, 256>>>(x, pat, edges);
    match_kernel<<<dim3(PT, MT), 256, SMEM_BYTES>>>((float*)d_out);
}